// round 15
// baseline (speedup 1.0000x reference)
#include <cuda_runtime.h>
#include <math.h>

#define NDIMS 3
#define HN    256
#define FN    16
#define MTOT  65536
#define TCOND 100
#define NJC   8            // j-chunks (proven shape)
#define JCW   (HN / NJC)   // 32

// ---- NUFFT parameters (validated: rel_err 2.14e-4) ----
#define NGRID 896          // sigma = 1.747
#define WK    5
#define NPAD  (NGRID + 5)  // 901 rows
#define RSTR  20           // 80B row stride
#define BETA  11.2113f
#define NSQ   64

#define NBLK  74           // eval blocks
#define SPB   886          // samples per eval block (74*886 >= 65536)
#define HALF  443          // samples per thread-slot

__device__ __align__(16) float g_tab[NDIMS][NPAD][RSTR];

// ---------------- packed f32x2 helpers ----------------
__device__ __forceinline__ unsigned long long pk2(float lo, float hi) {
    unsigned long long r;
    asm("mov.b64 %0, {%1, %2};" : "=l"(r) : "f"(lo), "f"(hi));
    return r;
}
__device__ __forceinline__ void upk2(unsigned long long v, float& lo, float& hi) {
    asm("mov.b64 {%0, %1}, %2;" : "=f"(lo), "=f"(hi) : "l"(v));
}
__device__ __forceinline__ unsigned long long fma2(unsigned long long a,
                                                   unsigned long long b,
                                                   unsigned long long c) {
    unsigned long long d;
    asm("fma.rn.f32x2 %0, %1, %2, %3;" : "=l"(d) : "l"(a), "l"(b), "l"(c));
    return d;
}
__device__ __forceinline__ unsigned long long mul2(unsigned long long a,
                                                   unsigned long long b) {
    unsigned long long d;
    asm("mul.rn.f32x2 %0, %1, %2;" : "=l"(d) : "l"(a), "l"(b));
    return d;
}
__device__ __forceinline__ float es_w(float z) {
    float s2 = fmaxf(1.0f - z * z, 0.0f);
    return __expf(BETA * (sqrtf(s2) - 1.0f));
}

// ---------------- kernel 1: fused psihat + fine-grid table build ----------------
// grid = (29, 3), block = 256 = 32 rows x 8 j-chunks (proven R12 shape).
#define PREP_SQ    0
#define PREP_PHI   257
#define PREP_A     328                       // 16B-aligned
#define PREP_B     (PREP_A + HN * FN)
#define PREP_PART  (PREP_B + HN * FN)
#define PREP_FLOATS (PREP_PART + 32 * NJC * FN)

__global__ void __launch_bounds__(256, 4)
prep_kernel(const float* __restrict__ fr, const float* __restrict__ fi) {
    extern __shared__ float sm[];
    float* sq   = sm + PREP_SQ;
    float* sphi = sm + PREP_PHI;
    float* sA   = sm + PREP_A;
    float* sB   = sm + PREP_B;
    float* part = sm + PREP_PART;

    const int n = blockIdx.y;
    const int tid = threadIdx.x;

    if (tid <= NSQ) {
        float z = -1.0f + (float)tid * (2.0f / NSQ);
        float phi = __expf(BETA * (sqrtf(fmaxf(1.0f - z * z, 0.0f)) - 1.0f));
        float cI = (tid == 0 || tid == NSQ) ? 1.0f : ((tid & 1) ? 4.0f : 2.0f);
        sphi[tid] = cI * phi * ((2.0f / NSQ) / 3.0f);
    }
    __syncthreads();

    {
        int k = tid + 1;
        float freq = (float)k * ((float)WK / (float)NGRID);
        float I = 0.0f;
#pragma unroll 4
        for (int i = 0; i <= NSQ; i++) {
            float z = -1.0f + (float)i * (2.0f / NSQ);
            I += sphi[i] * cospif(freq * z);
        }
        sq[k] = 2.0f / ((float)WK * I);
        if (tid == 0) {
            float I0 = 0.0f;
            for (int i = 0; i <= NSQ; i++) I0 += sphi[i];
            sq[0] = 2.0f / ((float)WK * I0);
        }
    }
    __syncthreads();

    for (int idx = tid; idx < HN * FN; idx += 256) {
        int f = idx & (FN - 1);
        int jm1 = idx >> 4;
        float q = sq[jm1 + 1];
        int src = (n * HN + (HN - 1 - jm1)) * FN + f;
        sA[idx] =  2.0f * q * fr[src];
        sB[idx] = -2.0f * q * fi[src];
    }
    __syncthreads();

    const int rl = tid & 31;
    const int jc = tid >> 5;
    const int r  = blockIdx.x * 32 + rl;
    {
        float xr = (float)(r - 2) * (1.0f / (float)NGRID);
        int jstart = jc * JCW + 1;
        float c0, s0, c1, s1;
        sincospif(2.0f * (float)jstart * xr, &s0, &c0);
        sincospif(2.0f * xr, &s1, &c1);
        unsigned long long cc = pk2(c0, c0), ss = pk2(s0, s0);
        unsigned long long C1 = pk2(c1, c1), S1 = pk2(s1, s1), nS1 = pk2(-s1, -s1);

        const ulonglong2* An = (const ulonglong2*)sA;
        const ulonglong2* Bn = (const ulonglong2*)sB;

        unsigned long long acc[8];
#pragma unroll
        for (int p = 0; p < 8; p++) acc[p] = 0ull;

        for (int jj = 0; jj < JCW; jj++) {
            int j0 = jc * JCW + jj;
            ulonglong2 a0 = An[4 * j0 + 0];
            ulonglong2 a1 = An[4 * j0 + 1];
            ulonglong2 a2 = An[4 * j0 + 2];
            ulonglong2 a3 = An[4 * j0 + 3];
            ulonglong2 b0 = Bn[4 * j0 + 0];
            ulonglong2 b1 = Bn[4 * j0 + 1];
            ulonglong2 b2 = Bn[4 * j0 + 2];
            ulonglong2 b3 = Bn[4 * j0 + 3];

            acc[0] = fma2(cc, a0.x, acc[0]);
            acc[1] = fma2(cc, a0.y, acc[1]);
            acc[2] = fma2(cc, a1.x, acc[2]);
            acc[3] = fma2(cc, a1.y, acc[3]);
            acc[4] = fma2(cc, a2.x, acc[4]);
            acc[5] = fma2(cc, a2.y, acc[5]);
            acc[6] = fma2(cc, a3.x, acc[6]);
            acc[7] = fma2(cc, a3.y, acc[7]);
            acc[0] = fma2(ss, b0.x, acc[0]);
            acc[1] = fma2(ss, b0.y, acc[1]);
            acc[2] = fma2(ss, b1.x, acc[2]);
            acc[3] = fma2(ss, b1.y, acc[3]);
            acc[4] = fma2(ss, b2.x, acc[4]);
            acc[5] = fma2(ss, b2.y, acc[5]);
            acc[6] = fma2(ss, b3.x, acc[6]);
            acc[7] = fma2(ss, b3.y, acc[7]);

            unsigned long long t0 = mul2(cc, C1);
            unsigned long long t1 = mul2(cc, S1);
            cc = fma2(ss, nS1, t0);
            ss = fma2(ss, C1,  t1);
        }

        float* pp = &part[(rl * NJC + jc) * FN];
#pragma unroll
        for (int p = 0; p < 8; p++) {
            float lo, hi;
            upk2(acc[p], lo, hi);
            pp[2 * p + 0] = lo;
            pp[2 * p + 1] = hi;
        }
    }
    __syncthreads();

    const float q0 = sq[0];
    for (int idx = tid; idx < 32 * FN; idx += 256) {
        int rl2 = idx >> 4;
        int f   = idx & (FN - 1);
        int rr  = blockIdx.x * 32 + rl2;
        if (rr < NPAD) {
            float v = q0;
#pragma unroll
            for (int q = 0; q < NJC; q++)
                v += part[(rl2 * NJC + q) * FN + f];
            g_tab[n][rr][f] = v;
        }
    }
}

// ---------------- gather helper: one (dim, f-half) window ----------------
struct Acc4 { unsigned long long a0, a1, a2, a3; };

__device__ __forceinline__ Acc4 gather_half(const float* rowp,
                                            unsigned long long w0,
                                            unsigned long long w1,
                                            unsigned long long w2,
                                            unsigned long long w3,
                                            unsigned long long w4) {
    ulonglong2 La0 = ((const ulonglong2*)(rowp + 0 * RSTR))[0];
    ulonglong2 Lb0 = ((const ulonglong2*)(rowp + 0 * RSTR))[1];
    ulonglong2 La1 = ((const ulonglong2*)(rowp + 1 * RSTR))[0];
    ulonglong2 Lb1 = ((const ulonglong2*)(rowp + 1 * RSTR))[1];
    ulonglong2 La2 = ((const ulonglong2*)(rowp + 2 * RSTR))[0];
    ulonglong2 Lb2 = ((const ulonglong2*)(rowp + 2 * RSTR))[1];
    ulonglong2 La3 = ((const ulonglong2*)(rowp + 3 * RSTR))[0];
    ulonglong2 Lb3 = ((const ulonglong2*)(rowp + 3 * RSTR))[1];
    ulonglong2 La4 = ((const ulonglong2*)(rowp + 4 * RSTR))[0];
    ulonglong2 Lb4 = ((const ulonglong2*)(rowp + 4 * RSTR))[1];

    Acc4 r;
    r.a0 = mul2(w0, La0.x);  r.a1 = mul2(w0, La0.y);
    r.a2 = mul2(w0, Lb0.x);  r.a3 = mul2(w0, Lb0.y);
    r.a0 = fma2(w1, La1.x, r.a0);  r.a1 = fma2(w1, La1.y, r.a1);
    r.a2 = fma2(w1, Lb1.x, r.a2);  r.a3 = fma2(w1, Lb1.y, r.a3);
    r.a0 = fma2(w2, La2.x, r.a0);  r.a1 = fma2(w2, La2.y, r.a1);
    r.a2 = fma2(w2, Lb2.x, r.a2);  r.a3 = fma2(w2, Lb2.y, r.a3);
    r.a0 = fma2(w3, La3.x, r.a0);  r.a1 = fma2(w3, La3.y, r.a1);
    r.a2 = fma2(w3, Lb3.x, r.a2);  r.a3 = fma2(w3, Lb3.y, r.a3);
    r.a0 = fma2(w4, La4.x, r.a0);  r.a1 = fma2(w4, La4.y, r.a1);
    r.a2 = fma2(w4, Lb4.x, r.a2);  r.a3 = fma2(w4, Lb4.y, r.a3);
    return r;
}

// ---------------- kernel 2: fused lamprep + eval, 2 samples/thread ----------------
// grid = 74, block = 512. Thread handles samples base+tid and base+HALF+tid.
#define TAB_FLOATS (NDIMS * NPAD * RSTR)     // 54060
#define EV_WSUM   TAB_FLOATS
#define EV_SC     (EV_WSUM + 12 * FN)
#define EV_LAM2   (EV_SC + NDIMS * FN)
#define EV_FLOATS (EV_LAM2 + FN)
#define EV_SMEM_BYTES (EV_FLOATS * 4)

__global__ void __launch_bounds__(512, 1)
eval_kernel(const float* __restrict__ x,
            const float* __restrict__ lam,
            float* __restrict__ out) {
    extern __shared__ float sm[];
    float* tab   = sm;
    float* wsum  = sm + EV_WSUM;
    float* sc    = sm + EV_SC;
    float* sLam2 = sm + EV_LAM2;

    const int tid = threadIdx.x;

    // table broadcast L2 -> smem (once per block, now amortized over 886 samples)
    {
        const float4* src = (const float4*)&g_tab[0][0][0];
        float4* dst = (float4*)tab;
        for (int idx = tid; idx < TAB_FLOATS / 4; idx += 512)
            dst[idx] = src[idx];
    }
    __syncthreads();

    // --- lamprep stage 1: warps 0..11 ---
    if (tid < NDIMS * 128) {
        int n = tid >> 7;
        int i = tid & 127;
        float val[FN];
#pragma unroll
        for (int f = 0; f < FN; f++) val[f] = 0.0f;
        if (i < TCOND) {
            float t = 0.01f + 0.01f * (float)i;
            float xg = t * (float)NGRID;
            float rc = floorf(xg + 0.5f);
            float dlt = xg - rc;
            int r0 = (int)rc;
            const float* rowp = tab + n * (NPAD * RSTR) + r0 * RSTR;
            float acc[FN];
#pragma unroll
            for (int f = 0; f < FN; f++) acc[f] = 0.0f;
#pragma unroll
            for (int tt = 0; tt < WK; tt++) {
                float wgt = es_w((dlt + (float)(2 - tt)) * 0.4f);
                const float4* p4 = (const float4*)(rowp + tt * RSTR);
#pragma unroll
                for (int cq = 0; cq < 4; cq++) {
                    float4 v = p4[cq];
                    acc[4 * cq + 0] = fmaf(wgt, v.x, acc[4 * cq + 0]);
                    acc[4 * cq + 1] = fmaf(wgt, v.y, acc[4 * cq + 1]);
                    acc[4 * cq + 2] = fmaf(wgt, v.z, acc[4 * cq + 2]);
                    acc[4 * cq + 3] = fmaf(wgt, v.w, acc[4 * cq + 3]);
                }
            }
            float wt = (i == 0 || i == TCOND - 1) ? 0.005f : 0.01f;
#pragma unroll
            for (int f = 0; f < FN; f++) val[f] = wt * fmaxf(acc[f], 0.0f);
        }
#pragma unroll
        for (int off = 16; off; off >>= 1)
#pragma unroll
            for (int f = 0; f < FN; f++)
                val[f] += __shfl_down_sync(0xffffffffu, val[f], off);
        if ((tid & 31) == 0) {
            int w = tid >> 5;
#pragma unroll
            for (int f = 0; f < FN; f++)
                wsum[w * FN + f] = val[f];
        }
    }

    // --- main eval: 2 samples per thread (A and B), interleaved gathers ---
    const int base = blockIdx.x * SPB;
    const bool actA = (tid < HALF);
    const int mA = base + (actA ? tid : 0);
    const int mBr = base + HALF + tid;
    const bool actB = (tid < HALF) && (mBr < MTOT);
    const int mB = actB ? mBr : mA;

    float xA[NDIMS], xB[NDIMS];
#pragma unroll
    for (int d = 0; d < NDIMS; d++) {
        xA[d] = x[3 * mA + d];
        xB[d] = x[3 * mB + d];
    }

    int rbA[NDIMS], rbB[NDIMS];
    float wA[NDIMS][WK], wB[NDIMS][WK];
#pragma unroll
    for (int n = 0; n < NDIMS; n++) {
        float xgA = xA[n] * (float)NGRID;
        float rcA = floorf(xgA + 0.5f);
        float dA  = xgA - rcA;
        rbA[n] = (int)rcA;
        float xgB = xB[n] * (float)NGRID;
        float rcB = floorf(xgB + 0.5f);
        float dB  = xgB - rcB;
        rbB[n] = (int)rcB;
#pragma unroll
        for (int t = 0; t < WK; t++) {
            wA[n][t] = es_w((dA + (float)(2 - t)) * 0.4f);
            wB[n][t] = es_w((dB + (float)(2 - t)) * 0.4f);
        }
    }

    unsigned long long prodA[8], prodB[8];
#pragma unroll
    for (int n = 0; n < NDIMS; n++) {
        const float* rowbA = tab + n * (NPAD * RSTR) + rbA[n] * RSTR;
        const float* rowbB = tab + n * (NPAD * RSTR) + rbB[n] * RSTR;

        unsigned long long wa0 = pk2(wA[n][0], wA[n][0]);
        unsigned long long wa1 = pk2(wA[n][1], wA[n][1]);
        unsigned long long wa2 = pk2(wA[n][2], wA[n][2]);
        unsigned long long wa3 = pk2(wA[n][3], wA[n][3]);
        unsigned long long wa4 = pk2(wA[n][4], wA[n][4]);
        unsigned long long wb0 = pk2(wB[n][0], wB[n][0]);
        unsigned long long wb1 = pk2(wB[n][1], wB[n][1]);
        unsigned long long wb2 = pk2(wB[n][2], wB[n][2]);
        unsigned long long wb3 = pk2(wB[n][3], wB[n][3]);
        unsigned long long wb4 = pk2(wB[n][4], wB[n][4]);

#pragma unroll
        for (int h = 0; h < 2; h++) {
            Acc4 aA = gather_half(rowbA + h * 8, wa0, wa1, wa2, wa3, wa4);
            Acc4 aB = gather_half(rowbB + h * 8, wb0, wb1, wb2, wb3, wb4);

            unsigned long long hA[4] = {aA.a0, aA.a1, aA.a2, aA.a3};
            unsigned long long hB[4] = {aB.a0, aB.a1, aB.a2, aB.a3};
#pragma unroll
            for (int q = 0; q < 4; q++) {
                float lo, hi;
                int p = h * 4 + q;
                upk2(hA[q], lo, hi);
                unsigned long long rA = pk2(fmaxf(lo, 0.0f), fmaxf(hi, 0.0f));
                prodA[p] = (n == 0) ? rA : mul2(prodA[p], rA);
                upk2(hB[q], lo, hi);
                unsigned long long rB = pk2(fmaxf(lo, 0.0f), fmaxf(hi, 0.0f));
                prodB[p] = (n == 0) ? rB : mul2(prodB[p], rB);
            }
        }
    }

    __syncthreads();   // wsum complete

    // --- lamprep stage 2 ---
    if (tid < NDIMS * FN) {
        int nn = tid >> 4;
        int f  = tid & 15;
        float s = wsum[(nn * 4 + 0) * FN + f] + wsum[(nn * 4 + 1) * FN + f]
                + wsum[(nn * 4 + 2) * FN + f] + wsum[(nn * 4 + 3) * FN + f];
        sc[tid] = 1.0f / s;
    }
    __syncthreads();
    if (tid < FN)
        sLam2[tid] = lam[tid] * sc[tid] * sc[FN + tid] * sc[2 * FN + tid];
    __syncthreads();

    // --- dot with lam', write both samples ---
    float sA = 0.0f, sB = 0.0f;
#pragma unroll
    for (int p = 0; p < 8; p++) {
        float lo, hi;
        int f0 = (p < 4) ? (2 * p) : (8 + 2 * (p - 4));
        upk2(prodA[p], lo, hi);
        sA = fmaf(lo, sLam2[f0], sA);
        sA = fmaf(hi, sLam2[f0 + 1], sA);
        upk2(prodB[p], lo, hi);
        sB = fmaf(lo, sLam2[f0], sB);
        sB = fmaf(hi, sLam2[f0 + 1], sB);
    }
    if (actA) out[mA] = sA;
    if (actB) out[mBr] = sB;
}

// ---------------- launch ----------------
extern "C" void kernel_launch(void* const* d_in, const int* in_sizes, int n_in,
                              void* d_out, int out_size) {
    const float* x   = (const float*)d_in[0];
    const float* fr  = (const float*)d_in[1];
    const float* fi  = (const float*)d_in[2];
    const float* lam = (const float*)d_in[3];
    float* out = (float*)d_out;

    const int prep_smem = PREP_FLOATS * (int)sizeof(float);
    cudaFuncSetAttribute(prep_kernel,
                         cudaFuncAttributeMaxDynamicSharedMemorySize, prep_smem);
    prep_kernel<<<dim3((NPAD + 31) / 32, NDIMS), 256, prep_smem>>>(fr, fi);

    cudaFuncSetAttribute(eval_kernel,
                         cudaFuncAttributeMaxDynamicSharedMemorySize, EV_SMEM_BYTES);
    eval_kernel<<<NBLK, 512, EV_SMEM_BYTES>>>(x, lam, out);
}

// round 16
// speedup vs baseline: 1.1604x; 1.1604x over previous
#include <cuda_runtime.h>
#include <math.h>

#define NDIMS 3
#define HN    256
#define FN    16
#define MTOT  65536
#define TCOND 100
#define NJC   8            // j-chunks (proven shape)
#define JCW   (HN / NJC)   // 32

// ---- NUFFT parameters (validated: rel_err 2.14e-4) ----
#define NGRID 896          // sigma = 1.747
#define WK    5
#define NPAD  (NGRID + 5)  // 901 rows
#define RSTR  20           // 80B row stride
#define BETA  11.2113f
#define NSQ   64

#define NBLK  148
#define SPB   443

__device__ __align__(16) float g_tab[NDIMS][NPAD][RSTR];

// ---------------- packed f32x2 helpers ----------------
__device__ __forceinline__ unsigned long long pk2(float lo, float hi) {
    unsigned long long r;
    asm("mov.b64 %0, {%1, %2};" : "=l"(r) : "f"(lo), "f"(hi));
    return r;
}
__device__ __forceinline__ void upk2(unsigned long long v, float& lo, float& hi) {
    asm("mov.b64 {%0, %1}, %2;" : "=f"(lo), "=f"(hi) : "l"(v));
}
__device__ __forceinline__ unsigned long long fma2(unsigned long long a,
                                                   unsigned long long b,
                                                   unsigned long long c) {
    unsigned long long d;
    asm("fma.rn.f32x2 %0, %1, %2, %3;" : "=l"(d) : "l"(a), "l"(b), "l"(c));
    return d;
}
__device__ __forceinline__ unsigned long long mul2(unsigned long long a,
                                                   unsigned long long b) {
    unsigned long long d;
    asm("mul.rn.f32x2 %0, %1, %2;" : "=l"(d) : "l"(a), "l"(b));
    return d;
}
__device__ __forceinline__ float es_w(float z) {
    float s2 = fmaxf(1.0f - z * z, 0.0f);
    return __expf(BETA * (sqrtf(s2) - 1.0f));
}

// ---------------- kernel 1: fused psihat + fine-grid table build ----------------
// grid = (29, 3), block = 256 = 32 rows x 8 j-chunks (proven R12 shape).
#define PREP_SQ    0
#define PREP_PHI   257
#define PREP_A     328                       // 16B-aligned
#define PREP_B     (PREP_A + HN * FN)
#define PREP_PART  (PREP_B + HN * FN)
#define PREP_FLOATS (PREP_PART + 32 * NJC * FN)

__global__ void __launch_bounds__(256, 4)
prep_kernel(const float* __restrict__ fr, const float* __restrict__ fi) {
    extern __shared__ float sm[];
    float* sq   = sm + PREP_SQ;
    float* sphi = sm + PREP_PHI;
    float* sA   = sm + PREP_A;
    float* sB   = sm + PREP_B;
    float* part = sm + PREP_PART;

    const int n = blockIdx.y;
    const int tid = threadIdx.x;

    if (tid <= NSQ) {
        float z = -1.0f + (float)tid * (2.0f / NSQ);
        float phi = __expf(BETA * (sqrtf(fmaxf(1.0f - z * z, 0.0f)) - 1.0f));
        float cI = (tid == 0 || tid == NSQ) ? 1.0f : ((tid & 1) ? 4.0f : 2.0f);
        sphi[tid] = cI * phi * ((2.0f / NSQ) / 3.0f);
    }
    __syncthreads();

    {
        int k = tid + 1;
        float freq = (float)k * ((float)WK / (float)NGRID);
        float I = 0.0f;
#pragma unroll 4
        for (int i = 0; i <= NSQ; i++) {
            float z = -1.0f + (float)i * (2.0f / NSQ);
            I += sphi[i] * cospif(freq * z);
        }
        sq[k] = 2.0f / ((float)WK * I);
        if (tid == 0) {
            float I0 = 0.0f;
            for (int i = 0; i <= NSQ; i++) I0 += sphi[i];
            sq[0] = 2.0f / ((float)WK * I0);
        }
    }
    __syncthreads();

    for (int idx = tid; idx < HN * FN; idx += 256) {
        int f = idx & (FN - 1);
        int jm1 = idx >> 4;
        float q = sq[jm1 + 1];
        int src = (n * HN + (HN - 1 - jm1)) * FN + f;
        sA[idx] =  2.0f * q * fr[src];
        sB[idx] = -2.0f * q * fi[src];
    }
    __syncthreads();

    const int rl = tid & 31;
    const int jc = tid >> 5;
    const int r  = blockIdx.x * 32 + rl;
    {
        float xr = (float)(r - 2) * (1.0f / (float)NGRID);
        int jstart = jc * JCW + 1;
        float c0, s0, c1, s1;
        sincospif(2.0f * (float)jstart * xr, &s0, &c0);
        sincospif(2.0f * xr, &s1, &c1);
        unsigned long long cc = pk2(c0, c0), ss = pk2(s0, s0);
        unsigned long long C1 = pk2(c1, c1), S1 = pk2(s1, s1), nS1 = pk2(-s1, -s1);

        const ulonglong2* An = (const ulonglong2*)sA;
        const ulonglong2* Bn = (const ulonglong2*)sB;

        unsigned long long acc[8];
#pragma unroll
        for (int p = 0; p < 8; p++) acc[p] = 0ull;

        for (int jj = 0; jj < JCW; jj++) {
            int j0 = jc * JCW + jj;
            ulonglong2 a0 = An[4 * j0 + 0];
            ulonglong2 a1 = An[4 * j0 + 1];
            ulonglong2 a2 = An[4 * j0 + 2];
            ulonglong2 a3 = An[4 * j0 + 3];
            ulonglong2 b0 = Bn[4 * j0 + 0];
            ulonglong2 b1 = Bn[4 * j0 + 1];
            ulonglong2 b2 = Bn[4 * j0 + 2];
            ulonglong2 b3 = Bn[4 * j0 + 3];

            acc[0] = fma2(cc, a0.x, acc[0]);
            acc[1] = fma2(cc, a0.y, acc[1]);
            acc[2] = fma2(cc, a1.x, acc[2]);
            acc[3] = fma2(cc, a1.y, acc[3]);
            acc[4] = fma2(cc, a2.x, acc[4]);
            acc[5] = fma2(cc, a2.y, acc[5]);
            acc[6] = fma2(cc, a3.x, acc[6]);
            acc[7] = fma2(cc, a3.y, acc[7]);
            acc[0] = fma2(ss, b0.x, acc[0]);
            acc[1] = fma2(ss, b0.y, acc[1]);
            acc[2] = fma2(ss, b1.x, acc[2]);
            acc[3] = fma2(ss, b1.y, acc[3]);
            acc[4] = fma2(ss, b2.x, acc[4]);
            acc[5] = fma2(ss, b2.y, acc[5]);
            acc[6] = fma2(ss, b3.x, acc[6]);
            acc[7] = fma2(ss, b3.y, acc[7]);

            unsigned long long t0 = mul2(cc, C1);
            unsigned long long t1 = mul2(cc, S1);
            cc = fma2(ss, nS1, t0);
            ss = fma2(ss, C1,  t1);
        }

        float* pp = &part[(rl * NJC + jc) * FN];
#pragma unroll
        for (int p = 0; p < 8; p++) {
            float lo, hi;
            upk2(acc[p], lo, hi);
            pp[2 * p + 0] = lo;
            pp[2 * p + 1] = hi;
        }
    }
    __syncthreads();

    const float q0 = sq[0];
    for (int idx = tid; idx < 32 * FN; idx += 256) {
        int rl2 = idx >> 4;
        int f   = idx & (FN - 1);
        int rr  = blockIdx.x * 32 + rl2;
        if (rr < NPAD) {
            float v = q0;
#pragma unroll
            for (int q = 0; q < NJC; q++)
                v += part[(rl2 * NJC + q) * FN + f];
            g_tab[n][rr][f] = v;
        }
    }
}

// ---------------- gather helper: one (dim, f-half) window, GMEM/L1 ----------------
struct Acc4 { unsigned long long a0, a1, a2, a3; };

__device__ __forceinline__ Acc4 gather_half(const float* __restrict__ rowp,
                                            unsigned long long w0,
                                            unsigned long long w1,
                                            unsigned long long w2,
                                            unsigned long long w3,
                                            unsigned long long w4) {
    ulonglong2 La0 = ((const ulonglong2*)(rowp + 0 * RSTR))[0];
    ulonglong2 Lb0 = ((const ulonglong2*)(rowp + 0 * RSTR))[1];
    ulonglong2 La1 = ((const ulonglong2*)(rowp + 1 * RSTR))[0];
    ulonglong2 Lb1 = ((const ulonglong2*)(rowp + 1 * RSTR))[1];
    ulonglong2 La2 = ((const ulonglong2*)(rowp + 2 * RSTR))[0];
    ulonglong2 Lb2 = ((const ulonglong2*)(rowp + 2 * RSTR))[1];
    ulonglong2 La3 = ((const ulonglong2*)(rowp + 3 * RSTR))[0];
    ulonglong2 Lb3 = ((const ulonglong2*)(rowp + 3 * RSTR))[1];
    ulonglong2 La4 = ((const ulonglong2*)(rowp + 4 * RSTR))[0];
    ulonglong2 Lb4 = ((const ulonglong2*)(rowp + 4 * RSTR))[1];

    Acc4 r;
    r.a0 = mul2(w0, La0.x);  r.a1 = mul2(w0, La0.y);
    r.a2 = mul2(w0, Lb0.x);  r.a3 = mul2(w0, Lb0.y);
    r.a0 = fma2(w1, La1.x, r.a0);  r.a1 = fma2(w1, La1.y, r.a1);
    r.a2 = fma2(w1, Lb1.x, r.a2);  r.a3 = fma2(w1, Lb1.y, r.a3);
    r.a0 = fma2(w2, La2.x, r.a0);  r.a1 = fma2(w2, La2.y, r.a1);
    r.a2 = fma2(w2, Lb2.x, r.a2);  r.a3 = fma2(w2, Lb2.y, r.a3);
    r.a0 = fma2(w3, La3.x, r.a0);  r.a1 = fma2(w3, La3.y, r.a1);
    r.a2 = fma2(w3, Lb3.x, r.a2);  r.a3 = fma2(w3, Lb3.y, r.a3);
    r.a0 = fma2(w4, La4.x, r.a0);  r.a1 = fma2(w4, La4.y, r.a1);
    r.a2 = fma2(w4, Lb4.x, r.a2);  r.a3 = fma2(w4, Lb4.y, r.a3);
    return r;
}

// ---------------- kernel 2: fused lamprep + eval, GMEM-gather (no smem table) ----------------
// grid = 148, block = 512, 1 thread/sample. Table lives in L1D (228KB >= 217KB).
__global__ void __launch_bounds__(512)
eval_kernel(const float* __restrict__ x,
            const float* __restrict__ lam,
            float* __restrict__ out) {
    __shared__ float wsum[12 * FN];
    __shared__ float sc[NDIMS * FN];
    __shared__ float sLam2[FN];

    const int tid = threadIdx.x;
    const float* __restrict__ tab = &g_tab[0][0][0];

    // --- lamprep stage 1: warps 0..11 (reads table from gmem/L1) ---
    if (tid < NDIMS * 128) {
        int n = tid >> 7;
        int i = tid & 127;
        float val[FN];
#pragma unroll
        for (int f = 0; f < FN; f++) val[f] = 0.0f;
        if (i < TCOND) {
            float t = 0.01f + 0.01f * (float)i;
            float xg = t * (float)NGRID;
            float rc = floorf(xg + 0.5f);
            float dlt = xg - rc;
            int r0 = (int)rc;
            const float* rowp = tab + n * (NPAD * RSTR) + r0 * RSTR;
            float acc[FN];
#pragma unroll
            for (int f = 0; f < FN; f++) acc[f] = 0.0f;
#pragma unroll
            for (int tt = 0; tt < WK; tt++) {
                float wgt = es_w((dlt + (float)(2 - tt)) * 0.4f);
                const float4* p4 = (const float4*)(rowp + tt * RSTR);
#pragma unroll
                for (int cq = 0; cq < 4; cq++) {
                    float4 v = p4[cq];
                    acc[4 * cq + 0] = fmaf(wgt, v.x, acc[4 * cq + 0]);
                    acc[4 * cq + 1] = fmaf(wgt, v.y, acc[4 * cq + 1]);
                    acc[4 * cq + 2] = fmaf(wgt, v.z, acc[4 * cq + 2]);
                    acc[4 * cq + 3] = fmaf(wgt, v.w, acc[4 * cq + 3]);
                }
            }
            float wt = (i == 0 || i == TCOND - 1) ? 0.005f : 0.01f;
#pragma unroll
            for (int f = 0; f < FN; f++) val[f] = wt * fmaxf(acc[f], 0.0f);
        }
#pragma unroll
        for (int off = 16; off; off >>= 1)
#pragma unroll
            for (int f = 0; f < FN; f++)
                val[f] += __shfl_down_sync(0xffffffffu, val[f], off);
        if ((tid & 31) == 0) {
            int w = tid >> 5;
#pragma unroll
            for (int f = 0; f < FN; f++)
                wsum[w * FN + f] = val[f];
        }
    }

    // --- main eval: 1 thread per sample, batched LDG gather ---
    const int base = blockIdx.x * SPB;
    const bool active = (tid < SPB) && (base + tid < MTOT);
    const int m = base + (active ? tid : 0);

    const float xv0 = x[3 * m + 0];
    const float xv1 = x[3 * m + 1];
    const float xv2 = x[3 * m + 2];

    int rbase[NDIMS];
    float wts[NDIMS][WK];
#pragma unroll
    for (int n = 0; n < NDIMS; n++) {
        const float xn = (n == 0) ? xv0 : (n == 1) ? xv1 : xv2;
        float xg = xn * (float)NGRID;
        float rc = floorf(xg + 0.5f);
        float dlt = xg - rc;
        rbase[n] = (int)rc;
#pragma unroll
        for (int t = 0; t < WK; t++)
            wts[n][t] = es_w((dlt + (float)(2 - t)) * 0.4f);
    }

    unsigned long long prod[8];
#pragma unroll
    for (int n = 0; n < NDIMS; n++) {
        const float* rowbase = tab + n * (NPAD * RSTR) + rbase[n] * RSTR;

        unsigned long long w0 = pk2(wts[n][0], wts[n][0]);
        unsigned long long w1 = pk2(wts[n][1], wts[n][1]);
        unsigned long long w2 = pk2(wts[n][2], wts[n][2]);
        unsigned long long w3 = pk2(wts[n][3], wts[n][3]);
        unsigned long long w4 = pk2(wts[n][4], wts[n][4]);

#pragma unroll
        for (int h = 0; h < 2; h++) {
            Acc4 a = gather_half(rowbase + h * 8, w0, w1, w2, w3, w4);
            unsigned long long hh[4] = {a.a0, a.a1, a.a2, a.a3};
#pragma unroll
            for (int q = 0; q < 4; q++) {
                float lo, hi;
                upk2(hh[q], lo, hi);
                unsigned long long r = pk2(fmaxf(lo, 0.0f), fmaxf(hi, 0.0f));
                int p = h * 4 + q;
                prod[p] = (n == 0) ? r : mul2(prod[p], r);
            }
        }
    }

    __syncthreads();   // wsum complete

    // --- lamprep stage 2 ---
    if (tid < NDIMS * FN) {
        int nn = tid >> 4;
        int f  = tid & 15;
        float s = wsum[(nn * 4 + 0) * FN + f] + wsum[(nn * 4 + 1) * FN + f]
                + wsum[(nn * 4 + 2) * FN + f] + wsum[(nn * 4 + 3) * FN + f];
        sc[tid] = 1.0f / s;
    }
    __syncthreads();
    if (tid < FN)
        sLam2[tid] = lam[tid] * sc[tid] * sc[FN + tid] * sc[2 * FN + tid];
    __syncthreads();

    // --- dot with lam', write ---
    float s = 0.0f;
#pragma unroll
    for (int p = 0; p < 8; p++) {
        float lo, hi;
        upk2(prod[p], lo, hi);
        int f0 = (p < 4) ? (2 * p) : (8 + 2 * (p - 4));
        s = fmaf(lo, sLam2[f0], s);
        s = fmaf(hi, sLam2[f0 + 1], s);
    }
    if (active) out[m] = s;
}

// ---------------- launch ----------------
extern "C" void kernel_launch(void* const* d_in, const int* in_sizes, int n_in,
                              void* d_out, int out_size) {
    const float* x   = (const float*)d_in[0];
    const float* fr  = (const float*)d_in[1];
    const float* fi  = (const float*)d_in[2];
    const float* lam = (const float*)d_in[3];
    float* out = (float*)d_out;

    const int prep_smem = PREP_FLOATS * (int)sizeof(float);
    cudaFuncSetAttribute(prep_kernel,
                         cudaFuncAttributeMaxDynamicSharedMemorySize, prep_smem);
    prep_kernel<<<dim3((NPAD + 31) / 32, NDIMS), 256, prep_smem>>>(fr, fi);

    eval_kernel<<<NBLK, 512>>>(x, lam, out);
}

// round 17
// speedup vs baseline: 1.1618x; 1.0013x over previous
#include <cuda_runtime.h>
#include <math.h>

#define NDIMS 3
#define HN    256
#define FN    16
#define MTOT  65536
#define TCOND 100
#define NJC   16           // j-chunks per row (512-thread prep)
#define JCW   (HN / NJC)   // 16

// ---- NUFFT parameters (validated: rel_err 2.14e-4) ----
#define NGRID 896          // sigma = 1.747
#define WK    5
#define NPAD  (NGRID + 5)  // 901 rows
#define RSTR  20           // 80B row stride
#define BETA  11.2113f
#define NSQ   64

#define NBLK  148
#define SPB   443

__device__ __align__(16) float g_tab[NDIMS][NPAD][RSTR];

// ---------------- packed f32x2 helpers ----------------
__device__ __forceinline__ unsigned long long pk2(float lo, float hi) {
    unsigned long long r;
    asm("mov.b64 %0, {%1, %2};" : "=l"(r) : "f"(lo), "f"(hi));
    return r;
}
__device__ __forceinline__ void upk2(unsigned long long v, float& lo, float& hi) {
    asm("mov.b64 {%0, %1}, %2;" : "=f"(lo), "=f"(hi) : "l"(v));
}
__device__ __forceinline__ unsigned long long fma2(unsigned long long a,
                                                   unsigned long long b,
                                                   unsigned long long c) {
    unsigned long long d;
    asm("fma.rn.f32x2 %0, %1, %2, %3;" : "=l"(d) : "l"(a), "l"(b), "l"(c));
    return d;
}
__device__ __forceinline__ unsigned long long mul2(unsigned long long a,
                                                   unsigned long long b) {
    unsigned long long d;
    asm("mul.rn.f32x2 %0, %1, %2;" : "=l"(d) : "l"(a), "l"(b));
    return d;
}
__device__ __forceinline__ float es_w(float z) {
    float s2 = fmaxf(1.0f - z * z, 0.0f);
    return __expf(BETA * (sqrtf(s2) - 1.0f));
}

// ---------------- kernel 1: fused psihat + fine-grid table build (v2) ----------------
// grid = (29, 3), block = 512 = 32 rows x 16 j-chunks of 16 j each.
// smem: sq[257]@0 | sphi[65]@257 | sA@328 (16B aligned) | sB@4424 | part@8520 [32*16*16]
#define PREP_SQ    0
#define PREP_PHI   257
#define PREP_A     328
#define PREP_B     (PREP_A + HN * FN)        // 4424
#define PREP_PART  (PREP_B + HN * FN)        // 8520
#define PREP_FLOATS (PREP_PART + 32 * NJC * FN)   // 16712 floats = 66.8KB

__global__ void __launch_bounds__(512, 1)
prep_kernel(const float* __restrict__ fr, const float* __restrict__ fi) {
    extern __shared__ float sm[];
    float* sq   = sm + PREP_SQ;
    float* sphi = sm + PREP_PHI;
    float* sA   = sm + PREP_A;
    float* sB   = sm + PREP_B;
    float* part = sm + PREP_PART;

    const int n = blockIdx.y;
    const int tid = threadIdx.x;

    // stage 0a: raw factor loads FIRST (LDG latency overlaps psihat compute)
    // sA = 2*fr (reversed j), sB = -2*fi (reversed j); q-scale applied later.
    for (int idx = tid; idx < HN * FN; idx += 512) {
        int f = idx & (FN - 1);
        int jm1 = idx >> 4;
        int src = (n * HN + (HN - 1 - jm1)) * FN + f;
        sA[idx] =  2.0f * fr[src];
        sB[idx] = -2.0f * fi[src];
    }

    // stage 0b: ES bump * simpson coeff * h/3 at 65 nodes
    if (tid <= NSQ) {
        float z = -1.0f + (float)tid * (2.0f / NSQ);
        float phi = __expf(BETA * (sqrtf(fmaxf(1.0f - z * z, 0.0f)) - 1.0f));
        float cI = (tid == 0 || tid == NSQ) ? 1.0f : ((tid & 1) ? 4.0f : 2.0f);
        sphi[tid] = cI * phi * ((2.0f / NSQ) / 3.0f);
    }
    __syncthreads();

    // stage 1: q_k = 2 / (w * I_k), threads 0..255 (k = tid+1), tid 0 also k=0
    if (tid < 256) {
        int k = tid + 1;
        float freq = (float)k * ((float)WK / (float)NGRID);
        float I = 0.0f;
#pragma unroll 4
        for (int i = 0; i <= NSQ; i++) {
            float z = -1.0f + (float)i * (2.0f / NSQ);
            I += sphi[i] * cospif(freq * z);
        }
        sq[k] = 2.0f / ((float)WK * I);
        if (tid == 0) {
            float I0 = 0.0f;
            for (int i = 0; i <= NSQ; i++) I0 += sphi[i];
            sq[0] = 2.0f / ((float)WK * I0);
        }
    }
    __syncthreads();

    // stage 2: scale factor tables in place by q_j
    for (int idx = tid; idx < HN * FN; idx += 512) {
        int jm1 = idx >> 4;
        float q = sq[jm1 + 1];
        sA[idx] *= q;
        sB[idx] *= q;
    }
    __syncthreads();

    // stage 3: series at 32 rows x 16 j-chunks (broadcast-safe mapping)
    const int rl = tid & 31;
    const int jc = tid >> 5;                 // 0..15
    const int r  = blockIdx.x * 32 + rl;
    {
        float xr = (float)(r - 2) * (1.0f / (float)NGRID);
        int jstart = jc * JCW + 1;
        float c0, s0, c1, s1;
        sincospif(2.0f * (float)jstart * xr, &s0, &c0);
        sincospif(2.0f * xr, &s1, &c1);
        unsigned long long cc = pk2(c0, c0), ss = pk2(s0, s0);
        unsigned long long C1 = pk2(c1, c1), S1 = pk2(s1, s1), nS1 = pk2(-s1, -s1);

        const ulonglong2* An = (const ulonglong2*)sA;
        const ulonglong2* Bn = (const ulonglong2*)sB;

        unsigned long long acc[8];
#pragma unroll
        for (int p = 0; p < 8; p++) acc[p] = 0ull;

#pragma unroll 2
        for (int jj = 0; jj < JCW; jj++) {
            int j0 = jc * JCW + jj;
            ulonglong2 a0 = An[4 * j0 + 0];
            ulonglong2 a1 = An[4 * j0 + 1];
            ulonglong2 a2 = An[4 * j0 + 2];
            ulonglong2 a3 = An[4 * j0 + 3];
            ulonglong2 b0 = Bn[4 * j0 + 0];
            ulonglong2 b1 = Bn[4 * j0 + 1];
            ulonglong2 b2 = Bn[4 * j0 + 2];
            ulonglong2 b3 = Bn[4 * j0 + 3];

            acc[0] = fma2(cc, a0.x, acc[0]);
            acc[1] = fma2(cc, a0.y, acc[1]);
            acc[2] = fma2(cc, a1.x, acc[2]);
            acc[3] = fma2(cc, a1.y, acc[3]);
            acc[4] = fma2(cc, a2.x, acc[4]);
            acc[5] = fma2(cc, a2.y, acc[5]);
            acc[6] = fma2(cc, a3.x, acc[6]);
            acc[7] = fma2(cc, a3.y, acc[7]);
            acc[0] = fma2(ss, b0.x, acc[0]);
            acc[1] = fma2(ss, b0.y, acc[1]);
            acc[2] = fma2(ss, b1.x, acc[2]);
            acc[3] = fma2(ss, b1.y, acc[3]);
            acc[4] = fma2(ss, b2.x, acc[4]);
            acc[5] = fma2(ss, b2.y, acc[5]);
            acc[6] = fma2(ss, b3.x, acc[6]);
            acc[7] = fma2(ss, b3.y, acc[7]);

            unsigned long long t0 = mul2(cc, C1);
            unsigned long long t1 = mul2(cc, S1);
            cc = fma2(ss, nS1, t0);
            ss = fma2(ss, C1,  t1);
        }

        float* pp = &part[(rl * NJC + jc) * FN];
#pragma unroll
        for (int p = 0; p < 8; p++) {
            float lo, hi;
            upk2(acc[p], lo, hi);
            pp[2 * p + 0] = lo;
            pp[2 * p + 1] = hi;
        }
    }
    __syncthreads();

    // stage 4: reduce — 512 threads = 32 rows x 16 f, sum 16 chunks each
    {
        const float q0 = sq[0];
        int rl2 = tid >> 4;
        int f   = tid & (FN - 1);
        int rr  = blockIdx.x * 32 + rl2;
        if (rr < NPAD) {
            float v = q0;
#pragma unroll
            for (int q = 0; q < NJC; q++)
                v += part[(rl2 * NJC + q) * FN + f];
            g_tab[n][rr][f] = v;
        }
    }
}

// ---------------- gather helper: one (dim, f-half) window, GMEM/L1 ----------------
struct Acc4 { unsigned long long a0, a1, a2, a3; };

__device__ __forceinline__ Acc4 gather_half(const float* __restrict__ rowp,
                                            unsigned long long w0,
                                            unsigned long long w1,
                                            unsigned long long w2,
                                            unsigned long long w3,
                                            unsigned long long w4) {
    ulonglong2 La0 = ((const ulonglong2*)(rowp + 0 * RSTR))[0];
    ulonglong2 Lb0 = ((const ulonglong2*)(rowp + 0 * RSTR))[1];
    ulonglong2 La1 = ((const ulonglong2*)(rowp + 1 * RSTR))[0];
    ulonglong2 Lb1 = ((const ulonglong2*)(rowp + 1 * RSTR))[1];
    ulonglong2 La2 = ((const ulonglong2*)(rowp + 2 * RSTR))[0];
    ulonglong2 Lb2 = ((const ulonglong2*)(rowp + 2 * RSTR))[1];
    ulonglong2 La3 = ((const ulonglong2*)(rowp + 3 * RSTR))[0];
    ulonglong2 Lb3 = ((const ulonglong2*)(rowp + 3 * RSTR))[1];
    ulonglong2 La4 = ((const ulonglong2*)(rowp + 4 * RSTR))[0];
    ulonglong2 Lb4 = ((const ulonglong2*)(rowp + 4 * RSTR))[1];

    Acc4 r;
    r.a0 = mul2(w0, La0.x);  r.a1 = mul2(w0, La0.y);
    r.a2 = mul2(w0, Lb0.x);  r.a3 = mul2(w0, Lb0.y);
    r.a0 = fma2(w1, La1.x, r.a0);  r.a1 = fma2(w1, La1.y, r.a1);
    r.a2 = fma2(w1, Lb1.x, r.a2);  r.a3 = fma2(w1, Lb1.y, r.a3);
    r.a0 = fma2(w2, La2.x, r.a0);  r.a1 = fma2(w2, La2.y, r.a1);
    r.a2 = fma2(w2, Lb2.x, r.a2);  r.a3 = fma2(w2, Lb2.y, r.a3);
    r.a0 = fma2(w3, La3.x, r.a0);  r.a1 = fma2(w3, La3.y, r.a1);
    r.a2 = fma2(w3, Lb3.x, r.a2);  r.a3 = fma2(w3, Lb3.y, r.a3);
    r.a0 = fma2(w4, La4.x, r.a0);  r.a1 = fma2(w4, La4.y, r.a1);
    r.a2 = fma2(w4, Lb4.x, r.a2);  r.a3 = fma2(w4, Lb4.y, r.a3);
    return r;
}

// ---------------- kernel 2: fused lamprep + eval, GMEM-gather (R16, unchanged) ----------------
__global__ void __launch_bounds__(512)
eval_kernel(const float* __restrict__ x,
            const float* __restrict__ lam,
            float* __restrict__ out) {
    __shared__ float wsum[12 * FN];
    __shared__ float sc[NDIMS * FN];
    __shared__ float sLam2[FN];

    const int tid = threadIdx.x;
    const float* __restrict__ tab = &g_tab[0][0][0];

    // --- lamprep stage 1: warps 0..11 ---
    if (tid < NDIMS * 128) {
        int n = tid >> 7;
        int i = tid & 127;
        float val[FN];
#pragma unroll
        for (int f = 0; f < FN; f++) val[f] = 0.0f;
        if (i < TCOND) {
            float t = 0.01f + 0.01f * (float)i;
            float xg = t * (float)NGRID;
            float rc = floorf(xg + 0.5f);
            float dlt = xg - rc;
            int r0 = (int)rc;
            const float* rowp = tab + n * (NPAD * RSTR) + r0 * RSTR;
            float acc[FN];
#pragma unroll
            for (int f = 0; f < FN; f++) acc[f] = 0.0f;
#pragma unroll
            for (int tt = 0; tt < WK; tt++) {
                float wgt = es_w((dlt + (float)(2 - tt)) * 0.4f);
                const float4* p4 = (const float4*)(rowp + tt * RSTR);
#pragma unroll
                for (int cq = 0; cq < 4; cq++) {
                    float4 v = p4[cq];
                    acc[4 * cq + 0] = fmaf(wgt, v.x, acc[4 * cq + 0]);
                    acc[4 * cq + 1] = fmaf(wgt, v.y, acc[4 * cq + 1]);
                    acc[4 * cq + 2] = fmaf(wgt, v.z, acc[4 * cq + 2]);
                    acc[4 * cq + 3] = fmaf(wgt, v.w, acc[4 * cq + 3]);
                }
            }
            float wt = (i == 0 || i == TCOND - 1) ? 0.005f : 0.01f;
#pragma unroll
            for (int f = 0; f < FN; f++) val[f] = wt * fmaxf(acc[f], 0.0f);
        }
#pragma unroll
        for (int off = 16; off; off >>= 1)
#pragma unroll
            for (int f = 0; f < FN; f++)
                val[f] += __shfl_down_sync(0xffffffffu, val[f], off);
        if ((tid & 31) == 0) {
            int w = tid >> 5;
#pragma unroll
            for (int f = 0; f < FN; f++)
                wsum[w * FN + f] = val[f];
        }
    }

    // --- main eval: 1 thread per sample, batched LDG gather ---
    const int base = blockIdx.x * SPB;
    const bool active = (tid < SPB) && (base + tid < MTOT);
    const int m = base + (active ? tid : 0);

    const float xv0 = x[3 * m + 0];
    const float xv1 = x[3 * m + 1];
    const float xv2 = x[3 * m + 2];

    int rbase[NDIMS];
    float wts[NDIMS][WK];
#pragma unroll
    for (int n = 0; n < NDIMS; n++) {
        const float xn = (n == 0) ? xv0 : (n == 1) ? xv1 : xv2;
        float xg = xn * (float)NGRID;
        float rc = floorf(xg + 0.5f);
        float dlt = xg - rc;
        rbase[n] = (int)rc;
#pragma unroll
        for (int t = 0; t < WK; t++)
            wts[n][t] = es_w((dlt + (float)(2 - t)) * 0.4f);
    }

    unsigned long long prod[8];
#pragma unroll
    for (int n = 0; n < NDIMS; n++) {
        const float* rowbase = tab + n * (NPAD * RSTR) + rbase[n] * RSTR;

        unsigned long long w0 = pk2(wts[n][0], wts[n][0]);
        unsigned long long w1 = pk2(wts[n][1], wts[n][1]);
        unsigned long long w2 = pk2(wts[n][2], wts[n][2]);
        unsigned long long w3 = pk2(wts[n][3], wts[n][3]);
        unsigned long long w4 = pk2(wts[n][4], wts[n][4]);

#pragma unroll
        for (int h = 0; h < 2; h++) {
            Acc4 a = gather_half(rowbase + h * 8, w0, w1, w2, w3, w4);
            unsigned long long hh[4] = {a.a0, a.a1, a.a2, a.a3};
#pragma unroll
            for (int q = 0; q < 4; q++) {
                float lo, hi;
                upk2(hh[q], lo, hi);
                unsigned long long r = pk2(fmaxf(lo, 0.0f), fmaxf(hi, 0.0f));
                int p = h * 4 + q;
                prod[p] = (n == 0) ? r : mul2(prod[p], r);
            }
        }
    }

    __syncthreads();   // wsum complete

    // --- lamprep stage 2 ---
    if (tid < NDIMS * FN) {
        int nn = tid >> 4;
        int f  = tid & 15;
        float s = wsum[(nn * 4 + 0) * FN + f] + wsum[(nn * 4 + 1) * FN + f]
                + wsum[(nn * 4 + 2) * FN + f] + wsum[(nn * 4 + 3) * FN + f];
        sc[tid] = 1.0f / s;
    }
    __syncthreads();
    if (tid < FN)
        sLam2[tid] = lam[tid] * sc[tid] * sc[FN + tid] * sc[2 * FN + tid];
    __syncthreads();

    // --- dot with lam', write ---
    float s = 0.0f;
#pragma unroll
    for (int p = 0; p < 8; p++) {
        float lo, hi;
        upk2(prod[p], lo, hi);
        int f0 = (p < 4) ? (2 * p) : (8 + 2 * (p - 4));
        s = fmaf(lo, sLam2[f0], s);
        s = fmaf(hi, sLam2[f0 + 1], s);
    }
    if (active) out[m] = s;
}

// ---------------- launch ----------------
extern "C" void kernel_launch(void* const* d_in, const int* in_sizes, int n_in,
                              void* d_out, int out_size) {
    const float* x   = (const float*)d_in[0];
    const float* fr  = (const float*)d_in[1];
    const float* fi  = (const float*)d_in[2];
    const float* lam = (const float*)d_in[3];
    float* out = (float*)d_out;

    const int prep_smem = PREP_FLOATS * (int)sizeof(float);
    cudaFuncSetAttribute(prep_kernel,
                         cudaFuncAttributeMaxDynamicSharedMemorySize, prep_smem);
    prep_kernel<<<dim3((NPAD + 31) / 32, NDIMS), 512, prep_smem>>>(fr, fi);

    eval_kernel<<<NBLK, 512>>>(x, lam, out);
}